// round 6
// baseline (speedup 1.0000x reference)
#include <cuda_runtime.h>
#include <cstdint>
#include <math.h>

namespace {

typedef unsigned long long ull;

constexpr int  B_  = 128;
constexpr int  T_  = 256;
constexpr int  R_  = 130;
constexpr int  H_  = 1024;
constexpr int  H3_ = 3072;
constexpr int  Z2_ = 256;
constexpr int  C_  = 24;
constexpr int  ZC_ = 280;                 // Z2 + C
constexpr long BT_ = (long)B_ * T_;       // 32768
constexpr long BH_ = (long)B_ * H_;

constexpr int NB = 128;   // persistent grid size (must all be co-resident)
constexpr int KC = 32;    // k-chunk (recurrent kernels)
constexpr int MT = 64;    // m tile (recurrent kernels)
constexpr int NJ = 16;    // j (h-column) tile (recurrent kernels)

// ------------------------- device scratch ----------------------------------
__device__ float g_hf[2][B_ * H_];
__device__ float g_hb[2][B_ * H_];
__device__ float g_h0[2][B_ * H_];
__device__ float g_h1[2][B_ * H_];
__device__ float g_gif[BT_ * H3_];        // encoder fwd input gates, row m=b*T+t
__device__ float g_gib[BT_ * H3_];        // encoder bwd input gates
__device__ float g_gid[BT_ * H3_];        // decoder dec_in input gates
__device__ float g_zi [B_ * H3_];         // z-part of decoder L1 gates (+b_ih_g)
__device__ float g_h1all[BT_ * H_];       // all decoder layer-2 hiddens
__device__ float g_henc[B_ * 2 * H_];
__device__ float g_var [B_ * Z2_];
__device__ float g_zbuf[B_ * ZC_];
__device__ float g_decin[BT_ * R_];
__device__ float g_logits[BT_ * R_];
__device__ unsigned g_bar_count;
__device__ volatile unsigned g_bar_gen;

// --------------------------- f32x2 helpers ---------------------------------
__device__ __forceinline__ ull pack2(float x, float y) {
    ull r; asm("mov.b64 %0, {%1, %2};" : "=l"(r) : "f"(x), "f"(y)); return r;
}
__device__ __forceinline__ float2 unpack2(ull v) {
    float2 f; asm("mov.b64 {%0, %1}, %2;" : "=f"(f.x), "=f"(f.y) : "l"(v)); return f;
}
__device__ __forceinline__ void fma2(ull& d, ull a, ull b) {
    asm("fma.rn.f32x2 %0, %1, %2, %0;" : "+l"(d) : "l"(a), "l"(b));
}
__device__ __forceinline__ float sigmoidf_(float x) { return 1.f / (1.f + expf(-x)); }

// ------------------------ software grid barrier ----------------------------
__device__ __forceinline__ void grid_barrier() {
    __syncthreads();
    if (threadIdx.x == 0) {
        unsigned gen = g_bar_gen;
        __threadfence();
        if (atomicAdd(&g_bar_count, 1u) == (unsigned)(NB - 1)) {
            g_bar_count = 0;
            __threadfence();
            g_bar_gen = gen + 1;
        } else {
            while (g_bar_gen == gen) { }
        }
        __threadfence();
    }
    __syncthreads();
}

// ------------------------------- GEMM --------------------------------------
// C[M,N] = A[M,K] (row-major) @ W[N,K]^T (row-major) + bias  (f32x2 packed)
struct GArgs {
    const float* A;  long lda;
    const float* W;  long ldw;
    const float* bias;
    float*       C;  long ldc;
    int M, N, K;
};

constexpr int GBM = 128, GBN = 128, GBK = 16;

// 256 threads; each thread computes 8 rows x 8 cols.
// Rows packed in f32x2 pairs (4 pairs); B duplicated as f32x2 in smem.
// B smem layout: Bs[kk][(n&7)*16 + (n>>3)] so inner-loop loads (c*16+tx) are
// conflict-free (consecutive ull across lanes).
__global__ void __launch_bounds__(256, 2) gemm_nt_kernel(GArgs g0, GArgs g1) {
    GArgs g = (blockIdx.z == 0) ? g0 : g1;
    const int bm = blockIdx.y * GBM;
    const int bn = blockIdx.x * GBN;
    if (bm >= g.M || bn >= g.N) return;

    __shared__ float As[GBK][GBM + 4];
    __shared__ ull   Bs[GBK][GBN + 1];

    const int tid = threadIdx.x;
    const int tx  = tid & 15;       // 16 col groups of 8
    const int ty  = tid >> 4;       // 16 row groups of 8
    const int r0  = ty * 8;

    ull acc[4][8];
#pragma unroll
    for (int p = 0; p < 4; p++)
#pragma unroll
        for (int c = 0; c < 8; c++) acc[p][c] = 0ull;

    for (int k0 = 0; k0 < g.K; k0 += GBK) {
        // load A: 128x16, 8 per thread
#pragma unroll
        for (int i = 0; i < 8; i++) {
            int idx = tid + i * 256;
            int m = idx >> 4, kk = idx & 15;
            int gm = bm + m, gk = k0 + kk;
            float v = 0.f;
            if (gm < g.M && gk < g.K) v = g.A[(long)gm * g.lda + gk];
            As[kk][m] = v;
        }
        // load B (duplicated to f32x2): 128x16, 8 per thread
#pragma unroll
        for (int i = 0; i < 8; i++) {
            int idx = tid + i * 256;
            int n = idx >> 4, kk = idx & 15;
            int gn = bn + n, gk = k0 + kk;
            float v = 0.f;
            if (gn < g.N && gk < g.K) v = g.W[(long)gn * g.ldw + gk];
            Bs[kk][(n & 7) * 16 + (n >> 3)] = pack2(v, v);
        }
        __syncthreads();
#pragma unroll
        for (int kk = 0; kk < GBK; kk++) {
            ull a[4], b[8];
#pragma unroll
            for (int p = 0; p < 4; p++) a[p] = *(const ull*)&As[kk][r0 + 2 * p];
#pragma unroll
            for (int c = 0; c < 8; c++) b[c] = Bs[kk][c * 16 + tx];
#pragma unroll
            for (int p = 0; p < 4; p++)
#pragma unroll
                for (int c = 0; c < 8; c++) fma2(acc[p][c], a[p], b[c]);
        }
        __syncthreads();
    }

#pragma unroll
    for (int p = 0; p < 4; p++) {
        int gm = bm + r0 + 2 * p;
#pragma unroll
        for (int c = 0; c < 8; c++) {
            int gn = bn + tx * 8 + c;
            if (gn >= g.N) continue;
            float2 v = unpack2(acc[p][c]);
            float bias = g.bias ? g.bias[gn] : 0.f;
            if (gm < g.M)     g.C[(long)gm * g.ldc + gn]       = v.x + bias;
            if (gm + 1 < g.M) g.C[(long)(gm + 1) * g.ldc + gn] = v.y + bias;
        }
    }
}

// -------------------- persistent encoder (bidirectional GRU) ---------------
__global__ void __launch_bounds__(256, 1)
encoder_kernel(const float* __restrict__ w_f, const float* __restrict__ bh_f,
               const float* __restrict__ w_b, const float* __restrict__ bh_b) {
    __shared__ float As[KC][MT + 2];                 // 8448 B
    __shared__ ull   Bs[3][KC][NJ + 1];              // 13056 B
    const int tid = threadIdx.x;
    const int tx  = tid & 15;       // h-column within tile
    const int ty  = tid >> 4;       // row group
    const int r0  = ty * 4;

#pragma unroll 1
    for (int t = 0; t < T_; t++) {
        const float* hfc = g_hf[t & 1];       float* hfn = g_hf[(t + 1) & 1];
        const float* hbc = g_hb[t & 1];       float* hbn = g_hb[(t + 1) & 1];
#pragma unroll 1
        for (int job = blockIdx.x; job < 256; job += NB) {
            const int jt  = job >> 2;
            const int dir = (job >> 1) & 1;
            const int mt  = job & 1;
            const float* h       = dir ? hbc : hfc;
            float*       hn_out  = dir ? hbn : hfn;
            const float* W       = dir ? w_b : w_f;
            const float* bh      = dir ? bh_b : bh_f;
            const float* gi_base = dir ? g_gib : g_gif;
            const int tstep = dir ? (T_ - 1 - t) : t;
            const int m0 = mt * MT;
            const int j0 = jt * NJ;

            ull ar[2] = {0ull, 0ull}, az[2] = {0ull, 0ull}, an[2] = {0ull, 0ull};
#pragma unroll 1
            for (int k0 = 0; k0 < H_; k0 += KC) {
                __syncthreads();
#pragma unroll
                for (int i = 0; i < 8; i++) {           // 64x32 A tile
                    int f = tid + i * 256;
                    int m = f >> 5, kk = f & 31;
                    As[kk][m] = h[(long)(m0 + m) * H_ + k0 + kk];
                }
#pragma unroll
                for (int i = 0; i < 6; i++) {           // 3x16x32 gate weights
                    int f = tid + i * 256;
                    int gg = f >> 9;
                    int r  = f & 511;
                    int n = r >> 5, kk = r & 31;
                    float w = W[(long)(gg * H_ + j0 + n) * H_ + k0 + kk];
                    Bs[gg][kk][n] = pack2(w, w);
                }
                __syncthreads();
#pragma unroll
                for (int kk = 0; kk < KC; kk++) {
                    ull a0 = *(const ull*)&As[kk][r0];
                    ull a1 = *(const ull*)&As[kk][r0 + 2];
                    ull br = Bs[0][kk][tx];
                    ull bz = Bs[1][kk][tx];
                    ull bn = Bs[2][kk][tx];
                    fma2(ar[0], a0, br); fma2(ar[1], a1, br);
                    fma2(az[0], a0, bz); fma2(az[1], a1, bz);
                    fma2(an[0], a0, bn); fma2(an[1], a1, bn);
                }
            }
            // fused GRU epilogue
            const int j = j0 + tx;
            const float bhr = bh[j], bhz = bh[H_ + j], bhn = bh[2 * H_ + j];
#pragma unroll
            for (int p = 0; p < 2; p++) {
                float2 hr2 = unpack2(ar[p]);
                float2 hz2 = unpack2(az[p]);
                float2 hn2 = unpack2(an[p]);
#pragma unroll
                for (int q = 0; q < 2; q++) {
                    int m = m0 + r0 + p * 2 + q;
                    float hr = (q ? hr2.y : hr2.x) + bhr;
                    float hz = (q ? hz2.y : hz2.x) + bhz;
                    float hn = (q ? hn2.y : hn2.x) + bhn;
                    long gio = ((long)m * T_ + tstep) * H3_ + j;
                    float ir  = gi_base[gio];
                    float iz  = gi_base[gio + H_];
                    float inn = gi_base[gio + 2 * H_];
                    float rr = sigmoidf_(ir + hr);
                    float u  = sigmoidf_(iz + hz);
                    float nn = tanhf(inn + rr * hn);
                    float hp = h[(long)m * H_ + j];
                    hn_out[(long)m * H_ + j] = (1.f - u) * nn + u * hp;
                }
            }
        }
        grid_barrier();
    }
}

// -------------------- persistent decoder (2-layer GRU) ---------------------
__global__ void __launch_bounds__(256, 1)
decoder_kernel(const float* __restrict__ w_hh_g,  const float* __restrict__ b_hh_g,
               const float* __restrict__ w_ih_g2, const float* __restrict__ w_hh_g2,
               const float* __restrict__ b_ih_g2, const float* __restrict__ b_hh_g2) {
    __shared__ __align__(16) char smem[43008];
    float* AsF  = (float*)smem;                 // [KC][66]   (A tile 1)
    float* As2F = (float*)(smem + 8448);        // [KC][66]   (A tile 2, phase B)
    ull*   BsA  = (ull*)(smem + 8448);          // phase A: 3*KC*17
    ull*   BsB  = (ull*)(smem + 16896);         // phase B: 6*KC*17

    const int tid = threadIdx.x;
    const int tx  = tid & 15;
    const int ty  = tid >> 4;
    const int r0  = ty * 4;
    const int job = blockIdx.x;                  // 128 jobs, 1 per block
    const int mt  = job & 1, jt = job >> 1;
    const int m0  = mt * MT, j0 = jt * NJ;
    const int j   = j0 + tx;

#pragma unroll 1
    for (int t = 0; t < T_; t++) {
        const float* h0c = g_h0[t & 1];
        float*       h0n = g_h0[(t + 1) & 1];
        // ---------------- phase A: layer-1 GRU ----------------
        {
            ull ar[2] = {0ull, 0ull}, az[2] = {0ull, 0ull}, an[2] = {0ull, 0ull};
#pragma unroll 1
            for (int k0 = 0; k0 < H_; k0 += KC) {
                __syncthreads();
#pragma unroll
                for (int i = 0; i < 8; i++) {
                    int f = tid + i * 256;
                    int m = f >> 5, kk = f & 31;
                    AsF[kk * 66 + m] = h0c[(long)(m0 + m) * H_ + k0 + kk];
                }
#pragma unroll
                for (int i = 0; i < 6; i++) {
                    int f = tid + i * 256;
                    int gg = f >> 9;
                    int r  = f & 511;
                    int n = r >> 5, kk = r & 31;
                    float w = w_hh_g[(long)(gg * H_ + j0 + n) * H_ + k0 + kk];
                    BsA[(gg * KC + kk) * 17 + n] = pack2(w, w);
                }
                __syncthreads();
#pragma unroll
                for (int kk = 0; kk < KC; kk++) {
                    ull a0 = *(const ull*)&AsF[kk * 66 + r0];
                    ull a1 = *(const ull*)&AsF[kk * 66 + r0 + 2];
                    ull br = BsA[(0 * KC + kk) * 17 + tx];
                    ull bz = BsA[(1 * KC + kk) * 17 + tx];
                    ull bn = BsA[(2 * KC + kk) * 17 + tx];
                    fma2(ar[0], a0, br); fma2(ar[1], a1, br);
                    fma2(az[0], a0, bz); fma2(az[1], a1, bz);
                    fma2(an[0], a0, bn); fma2(an[1], a1, bn);
                }
            }
            const float bhr = b_hh_g[j], bhz = b_hh_g[H_ + j], bhn = b_hh_g[2 * H_ + j];
#pragma unroll
            for (int p = 0; p < 2; p++) {
                float2 hr2 = unpack2(ar[p]);
                float2 hz2 = unpack2(az[p]);
                float2 hn2 = unpack2(an[p]);
#pragma unroll
                for (int q = 0; q < 2; q++) {
                    int m = m0 + r0 + p * 2 + q;
                    float hr = (q ? hr2.y : hr2.x) + bhr;
                    float hz = (q ? hz2.y : hz2.x) + bhz;
                    float hn = (q ? hn2.y : hn2.x) + bhn;
                    long zo = (long)m * H3_ + j;
                    long dof = ((long)m * T_ + t) * H3_ + j;
                    float ir  = g_gid[dof]           + g_zi[zo];
                    float iz  = g_gid[dof + H_]      + g_zi[zo + H_];
                    float inn = g_gid[dof + 2 * H_]  + g_zi[zo + 2 * H_];
                    float rr = sigmoidf_(ir + hr);
                    float u  = sigmoidf_(iz + hz);
                    float nn = tanhf(inn + rr * hn);
                    float hp = h0c[(long)m * H_ + j];
                    h0n[(long)m * H_ + j] = (1.f - u) * nn + u * hp;
                }
            }
        }
        grid_barrier();
        // ---------------- phase B: layer-2 GRU ----------------
        {
            const float* h1p = (t == 0) ? h0n : g_h1[t & 1];
            float*       h1n = g_h1[(t + 1) & 1];
            ull air[2] = {0ull, 0ull}, aiz[2] = {0ull, 0ull}, ain[2] = {0ull, 0ull};
            ull ahr[2] = {0ull, 0ull}, ahz[2] = {0ull, 0ull}, ahn[2] = {0ull, 0ull};
#pragma unroll 1
            for (int k0 = 0; k0 < H_; k0 += KC) {
                __syncthreads();
#pragma unroll
                for (int i = 0; i < 8; i++) {
                    int f = tid + i * 256;
                    int m = f >> 5, kk = f & 31;
                    AsF [kk * 66 + m] = h0n[(long)(m0 + m) * H_ + k0 + kk];
                    As2F[kk * 66 + m] = h1p[(long)(m0 + m) * H_ + k0 + kk];
                }
#pragma unroll
                for (int i = 0; i < 12; i++) {
                    int f = tid + i * 256;
                    int gg = f >> 9;
                    int r  = f & 511;
                    int n = r >> 5, kk = r & 31;
                    const float* W = (gg < 3) ? w_ih_g2 : w_hh_g2;
                    int gs = (gg < 3) ? gg : gg - 3;
                    float w = W[(long)(gs * H_ + j0 + n) * H_ + k0 + kk];
                    BsB[(gg * KC + kk) * 17 + n] = pack2(w, w);
                }
                __syncthreads();
#pragma unroll
                for (int kk = 0; kk < KC; kk++) {
                    ull a0 = *(const ull*)&AsF [kk * 66 + r0];
                    ull a1 = *(const ull*)&AsF [kk * 66 + r0 + 2];
                    ull c0 = *(const ull*)&As2F[kk * 66 + r0];
                    ull c1 = *(const ull*)&As2F[kk * 66 + r0 + 2];
                    ull bir = BsB[(0 * KC + kk) * 17 + tx];
                    ull biz = BsB[(1 * KC + kk) * 17 + tx];
                    ull bin = BsB[(2 * KC + kk) * 17 + tx];
                    ull bhr = BsB[(3 * KC + kk) * 17 + tx];
                    ull bhz = BsB[(4 * KC + kk) * 17 + tx];
                    ull bhn = BsB[(5 * KC + kk) * 17 + tx];
                    fma2(air[0], a0, bir); fma2(air[1], a1, bir);
                    fma2(aiz[0], a0, biz); fma2(aiz[1], a1, biz);
                    fma2(ain[0], a0, bin); fma2(ain[1], a1, bin);
                    fma2(ahr[0], c0, bhr); fma2(ahr[1], c1, bhr);
                    fma2(ahz[0], c0, bhz); fma2(ahz[1], c1, bhz);
                    fma2(ahn[0], c0, bhn); fma2(ahn[1], c1, bhn);
                }
            }
            const float bir = b_ih_g2[j], biz = b_ih_g2[H_ + j], bin2 = b_ih_g2[2 * H_ + j];
            const float bhr = b_hh_g2[j], bhz = b_hh_g2[H_ + j], bhn2 = b_hh_g2[2 * H_ + j];
#pragma unroll
            for (int p = 0; p < 2; p++) {
                float2 ir2 = unpack2(air[p]), iz2 = unpack2(aiz[p]), in2 = unpack2(ain[p]);
                float2 hr2 = unpack2(ahr[p]), hz2 = unpack2(ahz[p]), hn2 = unpack2(ahn[p]);
#pragma unroll
                for (int q = 0; q < 2; q++) {
                    int m = m0 + r0 + p * 2 + q;
                    float rr = sigmoidf_(((q ? ir2.y : ir2.x) + bir) + ((q ? hr2.y : hr2.x) + bhr));
                    float u  = sigmoidf_(((q ? iz2.y : iz2.x) + biz) + ((q ? hz2.y : hz2.x) + bhz));
                    float nn = tanhf(((q ? in2.y : in2.x) + bin2) + rr * ((q ? hn2.y : hn2.x) + bhn2));
                    float hp = h1p[(long)m * H_ + j];
                    float v = (1.f - u) * nn + u * hp;
                    h1n[(long)m * H_ + j] = v;
                    g_h1all[((long)m * T_ + t) * H_ + j] = v;
                }
            }
        }
        grid_barrier();
    }
}

// --------------------------- elementwise kernels ---------------------------
__global__ void init_kernel(const float* __restrict__ x) {
    long stride = (long)gridDim.x * blockDim.x;
    long i0 = (long)blockIdx.x * blockDim.x + threadIdx.x;
    if (i0 == 0) { g_bar_count = 0; g_bar_gen = 0; }
    for (long i = i0; i < BH_; i += stride) { g_hf[0][i] = 0.f; g_hb[0][i] = 0.f; }
    for (long i = i0; i < BT_ * R_; i += stride) {
        int  r = (int)(i % R_);
        long m = i / R_;
        int  t = (int)(m % T_);
        g_decin[i] = (t == 0) ? ((r == R_ - 1) ? 1.f : 0.f) : x[i - R_];
    }
}

__global__ void henc_kernel() {
    int i = blockIdx.x * blockDim.x + threadIdx.x;
    if (i >= B_ * H_) return;
    int b = i / H_, jj = i % H_;
    g_henc[(long)b * 2 * H_ + jj]      = g_hf[0][i];
    g_henc[(long)b * 2 * H_ + H_ + jj] = g_hb[0][i];
}

__global__ void zstd_kernel(const float* __restrict__ eps,
                            const float* __restrict__ chroma,
                            const float* __restrict__ mu_out,
                            float* __restrict__ std_out,
                            float* __restrict__ z_out) {
    int b = blockIdx.x;
    int jj = threadIdx.x;
    if (jj < Z2_) {
        float mu = mu_out[(long)b * Z2_ + jj];
        float sd = expf(g_var[(long)b * Z2_ + jj]);
        float z  = mu + sd * eps[(long)b * Z2_ + jj];
        std_out[(long)b * Z2_ + jj] = sd;
        z_out[(long)b * ZC_ + jj]   = z;
        g_zbuf[(long)b * ZC_ + jj]  = z;
    } else if (jj < ZC_) {
        float cv = chroma[(long)b * C_ + (jj - Z2_)];
        z_out[(long)b * ZC_ + jj]  = cv;
        g_zbuf[(long)b * ZC_ + jj] = cv;
    }
}

__global__ void logsoftmax_kernel(const float* __restrict__ logits,
                                  float* __restrict__ out) {
    long warp = ((long)blockIdx.x * blockDim.x + threadIdx.x) >> 5;
    int  lane = threadIdx.x & 31;
    if (warp >= BT_) return;
    const float* row = logits + warp * R_;
    float mx = -1e30f;
    for (int jj = lane; jj < R_; jj += 32) mx = fmaxf(mx, row[jj]);
#pragma unroll
    for (int o = 16; o; o >>= 1) mx = fmaxf(mx, __shfl_xor_sync(0xffffffff, mx, o));
    float s = 0.f;
    for (int jj = lane; jj < R_; jj += 32) s += expf(row[jj] - mx);
#pragma unroll
    for (int o = 16; o; o >>= 1) s += __shfl_xor_sync(0xffffffff, s, o);
    float lse = mx + logf(s);
    float* orow = out + warp * R_;
    for (int jj = lane; jj < R_; jj += 32) orow[jj] = row[jj] - lse;
}

// ------------------------------ host helpers -------------------------------
static void launch_gemm(const GArgs& a) {
    dim3 grid((a.N + GBN - 1) / GBN, (a.M + GBM - 1) / GBM, 1);
    gemm_nt_kernel<<<grid, 256>>>(a, a);
}
static void launch_gemm2(const GArgs& a, const GArgs& b) {
    int M = a.M > b.M ? a.M : b.M;
    int N = a.N > b.N ? a.N : b.N;
    dim3 grid((N + GBN - 1) / GBN, (M + GBM - 1) / GBM, 2);
    gemm_nt_kernel<<<grid, 256>>>(a, b);
}
template <typename Tp>
static float* sym_addr(Tp& sym) {
    void* p = nullptr;
    cudaGetSymbolAddress(&p, sym);
    return (float*)p;
}

} // anonymous namespace

extern "C" void kernel_launch(void* const* d_in, const int* in_sizes, int n_in,
                              void* d_out, int out_size) {
    (void)in_sizes; (void)n_in; (void)out_size;
    const float* x        = (const float*)d_in[0];
    const float* chroma   = (const float*)d_in[1];
    const float* eps      = (const float*)d_in[2];
    const float* w_ih_f   = (const float*)d_in[3];
    const float* w_hh_f   = (const float*)d_in[4];
    const float* b_ih_f   = (const float*)d_in[5];
    const float* b_hh_f   = (const float*)d_in[6];
    const float* w_ih_b   = (const float*)d_in[7];
    const float* w_hh_b   = (const float*)d_in[8];
    const float* b_ih_b   = (const float*)d_in[9];
    const float* b_hh_b   = (const float*)d_in[10];
    const float* w_mu     = (const float*)d_in[11];
    const float* b_mu     = (const float*)d_in[12];
    const float* w_var    = (const float*)d_in[13];
    const float* b_var    = (const float*)d_in[14];
    const float* w_init   = (const float*)d_in[15];
    const float* b_init   = (const float*)d_in[16];
    const float* w_ih_g   = (const float*)d_in[17];
    const float* w_hh_g   = (const float*)d_in[18];
    const float* b_ih_g   = (const float*)d_in[19];
    const float* b_hh_g   = (const float*)d_in[20];
    const float* w_ih_g2  = (const float*)d_in[21];
    const float* w_hh_g2  = (const float*)d_in[22];
    const float* b_ih_g2  = (const float*)d_in[23];
    const float* b_hh_g2  = (const float*)d_in[24];
    const float* w_out    = (const float*)d_in[25];
    const float* b_out    = (const float*)d_in[26];

    float* out = (float*)d_out;
    const long MU_OFF  = BT_ * R_;
    const long STD_OFF = MU_OFF + (long)B_ * Z2_;
    const long Z_OFF   = STD_OFF + (long)B_ * Z2_;

    float* p_gif   = sym_addr(g_gif);
    float* p_gib   = sym_addr(g_gib);
    float* p_gid   = sym_addr(g_gid);
    float* p_zi    = sym_addr(g_zi);
    float* p_h0    = sym_addr(g_h0);
    float* p_h1all = sym_addr(g_h1all);
    float* p_henc  = sym_addr(g_henc);
    float* p_var   = sym_addr(g_var);
    float* p_zbuf  = sym_addr(g_zbuf);
    float* p_decin = sym_addr(g_decin);
    float* p_logit = sym_addr(g_logits);

    // 1. prologue: zero h, reset barrier, build dec_in
    init_kernel<<<512, 256>>>(x);

    // 2. encoder input gates for all timesteps (both directions)
    GArgs gif{x, R_, w_ih_f, R_, b_ih_f, p_gif, H3_, (int)BT_, H3_, R_};
    GArgs gib{x, R_, w_ih_b, R_, b_ih_b, p_gib, H3_, (int)BT_, H3_, R_};
    launch_gemm2(gif, gib);

    // 3. decoder dec_in input gates (first 130 cols of w_ih_g)
    GArgs gid{p_decin, R_, w_ih_g, 410, nullptr, p_gid, H3_, (int)BT_, H3_, R_};
    launch_gemm(gid);

    // 4. persistent bidirectional encoder recurrence
    encoder_kernel<<<NB, 256>>>(w_hh_f, b_hh_f, w_hh_b, b_hh_b);

    // 5. concat final hiddens
    henc_kernel<<<(B_ * H_ + 255) / 256, 256>>>();

    // 6. VAE head
    GArgs gmu {p_henc, 2 * H_, w_mu,  2 * H_, b_mu,  out + MU_OFF, Z2_, B_, Z2_, 2 * H_};
    GArgs gvar{p_henc, 2 * H_, w_var, 2 * H_, b_var, p_var,        Z2_, B_, Z2_, 2 * H_};
    launch_gemm2(gmu, gvar);

    // 7. reparameterize + concat chroma
    zstd_kernel<<<B_, 288>>>(eps, chroma, out + MU_OFF, out + STD_OFF, out + Z_OFF);

    // 8. hx0 = z @ w_init^T + b_init ; zi = z @ w_ih_g[:,130:]^T + b_ih_g
    GArgs ghx0{p_zbuf, ZC_, w_init, ZC_, b_init, p_h0, H_, B_, H_, ZC_};
    GArgs gzi {p_zbuf, ZC_, w_ih_g + 130, 410, b_ih_g, p_zi, H3_, B_, H3_, ZC_};
    launch_gemm2(ghx0, gzi);

    // 9. persistent 2-layer decoder recurrence
    decoder_kernel<<<NB, 256>>>(w_hh_g, b_hh_g, w_ih_g2, w_hh_g2, b_ih_g2, b_hh_g2);

    // 10. batched output projection
    GArgs glog{p_h1all, H_, w_out, H_, b_out, p_logit, R_, (int)BT_, R_, H_};
    launch_gemm(glog);

    // 11. log_softmax
    logsoftmax_kernel<<<(int)((BT_ * 32 + 255) / 256), 256>>>(p_logit, out);
}

// round 7
// speedup vs baseline: 2.6662x; 2.6662x over previous
#include <cuda_runtime.h>
#include <cuda_bf16.h>
#include <cstdint>
#include <math.h>

namespace {

typedef unsigned long long ull;

constexpr int  B_  = 128;
constexpr int  T_  = 256;
constexpr int  R_  = 130;
constexpr int  H_  = 1024;
constexpr int  H3_ = 3072;
constexpr int  Z2_ = 256;
constexpr int  C_  = 24;
constexpr int  ZC_ = 280;                 // Z2 + C
constexpr long BT_ = (long)B_ * T_;       // 32768
constexpr long BH_ = (long)B_ * H_;
constexpr long WN_ = (long)H3_ * H_;      // 3.1M weights per matrix

constexpr int NB = 128;   // persistent grid size (must all be co-resident)

// smem geometry for the mma passes (k-chunk = 64 bf16, padded row = 72 bf16)
constexpr int KCH    = 64;
constexpr int ROWB   = 144;               // bytes per padded row
constexpr int ABYTES = 128 * ROWB;        // 18432
constexpr int BBYTES = 24  * ROWB;        // 3456
constexpr int STAGE  = 2 * ABYTES + 2 * BBYTES;  // 43776
constexpr int SMEM_DYN = 2 * STAGE;       // 87552

// ------------------------- device scratch ----------------------------------
__device__ float g_hf[2][B_ * H_];
__device__ float g_hb[2][B_ * H_];
__device__ float g_h0[2][B_ * H_];
__device__ float g_h1[2][B_ * H_];
__device__ __nv_bfloat16 g_hfhi[2][B_ * H_], g_hflo[2][B_ * H_];
__device__ __nv_bfloat16 g_hbhi[2][B_ * H_], g_hblo[2][B_ * H_];
__device__ __nv_bfloat16 g_h0hi[2][B_ * H_], g_h0lo[2][B_ * H_];
__device__ __nv_bfloat16 g_h1hi[2][B_ * H_], g_h1lo[2][B_ * H_];
__device__ __nv_bfloat16 g_whhf_hi[WN_], g_whhf_lo[WN_];
__device__ __nv_bfloat16 g_whhb_hi[WN_], g_whhb_lo[WN_];
__device__ __nv_bfloat16 g_whhg_hi[WN_], g_whhg_lo[WN_];
__device__ __nv_bfloat16 g_wihg2_hi[WN_], g_wihg2_lo[WN_];
__device__ __nv_bfloat16 g_whhg2_hi[WN_], g_whhg2_lo[WN_];
__device__ float g_gif[BT_ * H3_];        // encoder fwd input gates, row m=b*T+t
__device__ float g_gib[BT_ * H3_];        // encoder bwd input gates
__device__ float g_gid[BT_ * H3_];        // decoder dec_in input gates
__device__ float g_zi [B_ * H3_];         // z-part of decoder L1 gates (+b_ih_g)
__device__ float g_h1all[BT_ * H_];       // all decoder layer-2 hiddens
__device__ float g_henc[B_ * 2 * H_];
__device__ float g_var [B_ * Z2_];
__device__ float g_zbuf[B_ * ZC_];
__device__ float g_decin[BT_ * R_];
__device__ float g_logits[BT_ * R_];
__device__ unsigned g_bar_count;
__device__ volatile unsigned g_bar_gen;

// --------------------------- small helpers ---------------------------------
__device__ __forceinline__ ull pack2(float x, float y) {
    ull r; asm("mov.b64 %0, {%1, %2};" : "=l"(r) : "f"(x), "f"(y)); return r;
}
__device__ __forceinline__ float2 unpack2(ull v) {
    float2 f; asm("mov.b64 {%0, %1}, %2;" : "=f"(f.x), "=f"(f.y) : "l"(v)); return f;
}
__device__ __forceinline__ void fma2(ull& d, ull a, ull b) {
    asm("fma.rn.f32x2 %0, %1, %2, %0;" : "+l"(d) : "l"(a), "l"(b));
}
__device__ __forceinline__ float sigmoidf_(float x) { return 1.f / (1.f + expf(-x)); }

__device__ __forceinline__ void ldsm4(uint32_t r[4], uint32_t addr) {
    asm volatile("ldmatrix.sync.aligned.m8n8.x4.shared.b16 {%0,%1,%2,%3}, [%4];"
                 : "=r"(r[0]), "=r"(r[1]), "=r"(r[2]), "=r"(r[3]) : "r"(addr));
}
__device__ __forceinline__ void ldsm2(uint32_t r[2], uint32_t addr) {
    asm volatile("ldmatrix.sync.aligned.m8n8.x2.shared.b16 {%0,%1}, [%2];"
                 : "=r"(r[0]), "=r"(r[1]) : "r"(addr));
}
__device__ __forceinline__ void mma16816(float d[4], const uint32_t a[4], const uint32_t b[2]) {
    asm volatile(
        "mma.sync.aligned.m16n8k16.row.col.f32.bf16.bf16.f32 "
        "{%0,%1,%2,%3}, {%4,%5,%6,%7}, {%8,%9}, {%0,%1,%2,%3};"
        : "+f"(d[0]), "+f"(d[1]), "+f"(d[2]), "+f"(d[3])
        : "r"(a[0]), "r"(a[1]), "r"(a[2]), "r"(a[3]), "r"(b[0]), "r"(b[1]));
}
__device__ __forceinline__ void cpa16(uint32_t dst, const void* src) {
    asm volatile("cp.async.cg.shared.global [%0], [%1], 16;" :: "r"(dst), "l"(src));
}
__device__ __forceinline__ void cp_commit() { asm volatile("cp.async.commit_group;"); }
template <int N> __device__ __forceinline__ void cp_wait() {
    asm volatile("cp.async.wait_group %0;" :: "n"(N));
}

// ------------------------ software grid barrier ----------------------------
__device__ __forceinline__ void grid_barrier() {
    __syncthreads();
    if (threadIdx.x == 0) {
        unsigned gen = g_bar_gen;
        __threadfence();
        if (atomicAdd(&g_bar_count, 1u) == (unsigned)(NB - 1)) {
            g_bar_count = 0;
            __threadfence();
            g_bar_gen = gen + 1;
        } else {
            while (g_bar_gen == gen) { }
        }
        __threadfence();
    }
    __syncthreads();
}

// --------------------- split-bf16 mma pass ----------------------------------
// Computes acc[g][4] (+=) for C[128 x 24] tile: rows = batch, cols = gate g
// columns j0..j0+7 of W (row-block g*1024 + j0), K = 1024.
// A: [128 x 1024] bf16 hi/lo (row stride H_). W: [3072 x 1024] bf16 hi/lo.
__device__ __forceinline__ void mma_pass(
    const __nv_bfloat16* __restrict__ Ah, const __nv_bfloat16* __restrict__ Al,
    const __nv_bfloat16* __restrict__ Wh, const __nv_bfloat16* __restrict__ Wl,
    int j0, uint32_t sm, float acc[3][4])
{
    const int tid  = threadIdx.x;
    const int lane = tid & 31;
    const int m0   = (tid >> 5) * 16;

    const int arow  = m0 + (lane & 15);
    const int ahalf = (lane >> 4) * 16;
    const int brow  = lane & 7;
    const int bhalf = ((lane >> 3) & 1) * 16;

    auto issue = [&](int c, int st) {
        uint32_t base = sm + st * STAGE;
        int k0 = c * KCH;
#pragma unroll
        for (int i = 0; i < 4; i++) {
            int u = tid + i * 256;
            int row = u >> 3, seg = u & 7;
            uint32_t d = base + row * ROWB + seg * 16;
            const long off = (long)row * H_ + k0 + seg * 8;
            cpa16(d, Ah + off);
            cpa16(d + ABYTES, Al + off);
        }
        if (tid < 192) {
            int row = tid >> 3, seg = tid & 7;
            int gg = row >> 3, rr = row & 7;
            long woff = (long)(gg * H_ + j0 + rr) * H_ + k0 + seg * 8;
            uint32_t d = base + 2 * ABYTES + row * ROWB + seg * 16;
            cpa16(d, Wh + woff);
            cpa16(d + BBYTES, Wl + woff);
        }
    };

    issue(0, 0); cp_commit();
#pragma unroll 1
    for (int c = 0; c < 16; c++) {
        if (c < 15) { issue(c + 1, (c + 1) & 1); cp_commit(); cp_wait<1>(); }
        else        { cp_wait<0>(); }
        __syncthreads();
        uint32_t base = sm + (c & 1) * STAGE;
#pragma unroll
        for (int s = 0; s < 4; s++) {
            uint32_t aoff = base + arow * ROWB + ahalf + s * 32;
            uint32_t a_hi[4], a_lo[4];
            ldsm4(a_hi, aoff);
            ldsm4(a_lo, aoff + ABYTES);
#pragma unroll
            for (int g = 0; g < 3; g++) {
                uint32_t boff = base + 2 * ABYTES + (g * 8 + brow) * ROWB + bhalf + s * 32;
                uint32_t b_hi[2], b_lo[2];
                ldsm2(b_hi, boff);
                ldsm2(b_lo, boff + BBYTES);
                mma16816(acc[g], a_hi, b_hi);
                mma16816(acc[g], a_hi, b_lo);
                mma16816(acc[g], a_lo, b_hi);
            }
        }
        __syncthreads();
    }
}

// Fused GRU epilogue on mma accum fragments (single input-gate source).
__device__ __forceinline__ void gru_epi(
    const float acc[3][4], const float* __restrict__ gi, int tstep,
    const float bh[6], const float* __restrict__ hprev,
    float* __restrict__ hn, __nv_bfloat16* __restrict__ hhi,
    __nv_bfloat16* __restrict__ hlo, int m0, int lane, int jj)
{
#pragma unroll
    for (int half = 0; half < 2; half++) {
        int m = m0 + (lane >> 2) + half * 8;
        long gb = ((long)m * T_ + tstep) * H3_ + jj;
        float2 gr = *(const float2*)(gi + gb);
        float2 gz = *(const float2*)(gi + gb + H_);
        float2 gn = *(const float2*)(gi + gb + 2 * H_);
        float2 hp = *(const float2*)(hprev + (long)m * H_ + jj);
        float r0 = sigmoidf_(gr.x + acc[0][half * 2]     + bh[0]);
        float r1 = sigmoidf_(gr.y + acc[0][half * 2 + 1] + bh[1]);
        float u0 = sigmoidf_(gz.x + acc[1][half * 2]     + bh[2]);
        float u1 = sigmoidf_(gz.y + acc[1][half * 2 + 1] + bh[3]);
        float n0 = tanhf(gn.x + r0 * (acc[2][half * 2]     + bh[4]));
        float n1 = tanhf(gn.y + r1 * (acc[2][half * 2 + 1] + bh[5]));
        float v0 = (1.f - u0) * n0 + u0 * hp.x;
        float v1 = (1.f - u1) * n1 + u1 * hp.y;
        *(float2*)(hn + (long)m * H_ + jj) = make_float2(v0, v1);
        __nv_bfloat16 h0 = __float2bfloat16(v0);
        __nv_bfloat16 h1 = __float2bfloat16(v1);
        *(__nv_bfloat162*)(hhi + (long)m * H_ + jj) = __nv_bfloat162(h0, h1);
        *(__nv_bfloat162*)(hlo + (long)m * H_ + jj) = __nv_bfloat162(
            __float2bfloat16(v0 - __bfloat162float(h0)),
            __float2bfloat16(v1 - __bfloat162float(h1)));
    }
}

// -------------------- persistent encoder (bidirectional GRU) ---------------
__global__ void __launch_bounds__(256, 1)
encoder_kernel(const float* __restrict__ bh_f, const float* __restrict__ bh_b) {
    extern __shared__ char smem[];
    uint32_t sm = (uint32_t)__cvta_generic_to_shared(smem);
    const int tid = threadIdx.x, lane = tid & 31;
    const int m0 = (tid >> 5) * 16;
    const int j0 = blockIdx.x * 8;
    const int jj = j0 + (lane & 3) * 2;

    float bf6[6], bb6[6];
#pragma unroll
    for (int g = 0; g < 3; g++) {
        bf6[g * 2] = bh_f[g * H_ + jj];  bf6[g * 2 + 1] = bh_f[g * H_ + jj + 1];
        bb6[g * 2] = bh_b[g * H_ + jj];  bb6[g * 2 + 1] = bh_b[g * H_ + jj + 1];
    }

#pragma unroll 1
    for (int t = 0; t < T_; t++) {
        const int cur = t & 1, nxt = cur ^ 1;
        {   // forward direction
            float acc[3][4] = {};
            mma_pass(g_hfhi[cur], g_hflo[cur], g_whhf_hi, g_whhf_lo, j0, sm, acc);
            gru_epi(acc, g_gif, t, bf6, g_hf[cur],
                    g_hf[nxt], g_hfhi[nxt], g_hflo[nxt], m0, lane, jj);
        }
        {   // backward direction
            float acc[3][4] = {};
            mma_pass(g_hbhi[cur], g_hblo[cur], g_whhb_hi, g_whhb_lo, j0, sm, acc);
            gru_epi(acc, g_gib, T_ - 1 - t, bb6, g_hb[cur],
                    g_hb[nxt], g_hbhi[nxt], g_hblo[nxt], m0, lane, jj);
        }
        grid_barrier();
    }
}

// -------------------- persistent decoder (2-layer GRU) ---------------------
__global__ void __launch_bounds__(256, 1)
decoder_kernel(const float* __restrict__ b_hh_g,
               const float* __restrict__ b_ih_g2, const float* __restrict__ b_hh_g2) {
    extern __shared__ char smem[];
    uint32_t sm = (uint32_t)__cvta_generic_to_shared(smem);
    const int tid = threadIdx.x, lane = tid & 31;
    const int m0 = (tid >> 5) * 16;
    const int j0 = blockIdx.x * 8;
    const int jj = j0 + (lane & 3) * 2;

    float bg6[6], bi6[6], bh6[6];
#pragma unroll
    for (int g = 0; g < 3; g++) {
        bg6[g * 2] = b_hh_g[g * H_ + jj];  bg6[g * 2 + 1] = b_hh_g[g * H_ + jj + 1];
        bi6[g * 2] = b_ih_g2[g * H_ + jj]; bi6[g * 2 + 1] = b_ih_g2[g * H_ + jj + 1];
        bh6[g * 2] = b_hh_g2[g * H_ + jj]; bh6[g * 2 + 1] = b_hh_g2[g * H_ + jj + 1];
    }

#pragma unroll 1
    for (int t = 0; t < T_; t++) {
        const int cur = t & 1, nxt = cur ^ 1;
        // ------- phase A: layer-1 GRU -------
        {
            float acc[3][4] = {};
            mma_pass(g_h0hi[cur], g_h0lo[cur], g_whhg_hi, g_whhg_lo, j0, sm, acc);
            // epilogue: input gates = g_gid (per t) + g_zi (time-invariant)
#pragma unroll
            for (int half = 0; half < 2; half++) {
                int m = m0 + (lane >> 2) + half * 8;
                long gb = ((long)m * T_ + t) * H3_ + jj;
                long zb = (long)m * H3_ + jj;
                float2 gr = *(const float2*)(g_gid + gb);
                float2 gz = *(const float2*)(g_gid + gb + H_);
                float2 gn = *(const float2*)(g_gid + gb + 2 * H_);
                float2 zr = *(const float2*)(g_zi + zb);
                float2 zz = *(const float2*)(g_zi + zb + H_);
                float2 zn = *(const float2*)(g_zi + zb + 2 * H_);
                float2 hp = *(const float2*)(g_h0[cur] + (long)m * H_ + jj);
                float r0 = sigmoidf_(gr.x + zr.x + acc[0][half * 2]     + bg6[0]);
                float r1 = sigmoidf_(gr.y + zr.y + acc[0][half * 2 + 1] + bg6[1]);
                float u0 = sigmoidf_(gz.x + zz.x + acc[1][half * 2]     + bg6[2]);
                float u1 = sigmoidf_(gz.y + zz.y + acc[1][half * 2 + 1] + bg6[3]);
                float n0 = tanhf(gn.x + zn.x + r0 * (acc[2][half * 2]     + bg6[4]));
                float n1 = tanhf(gn.y + zn.y + r1 * (acc[2][half * 2 + 1] + bg6[5]));
                float v0 = (1.f - u0) * n0 + u0 * hp.x;
                float v1 = (1.f - u1) * n1 + u1 * hp.y;
                *(float2*)(g_h0[nxt] + (long)m * H_ + jj) = make_float2(v0, v1);
                __nv_bfloat16 h0b = __float2bfloat16(v0);
                __nv_bfloat16 h1b = __float2bfloat16(v1);
                *(__nv_bfloat162*)(g_h0hi[nxt] + (long)m * H_ + jj) = __nv_bfloat162(h0b, h1b);
                *(__nv_bfloat162*)(g_h0lo[nxt] + (long)m * H_ + jj) = __nv_bfloat162(
                    __float2bfloat16(v0 - __bfloat162float(h0b)),
                    __float2bfloat16(v1 - __bfloat162float(h1b)));
            }
        }
        grid_barrier();
        // ------- phase B: layer-2 GRU -------
        {
            const __nv_bfloat16* h1p_hi = (t == 0) ? g_h0hi[nxt] : g_h1hi[cur];
            const __nv_bfloat16* h1p_lo = (t == 0) ? g_h0lo[nxt] : g_h1lo[cur];
            const float*         h1p_f  = (t == 0) ? g_h0[nxt]   : g_h1[cur];
            float accI[3][4] = {};
            float accH[3][4] = {};
            mma_pass(g_h0hi[nxt], g_h0lo[nxt], g_wihg2_hi, g_wihg2_lo, j0, sm, accI);
            mma_pass(h1p_hi, h1p_lo, g_whhg2_hi, g_whhg2_lo, j0, sm, accH);
#pragma unroll
            for (int half = 0; half < 2; half++) {
                int m = m0 + (lane >> 2) + half * 8;
                float2 hp = *(const float2*)(h1p_f + (long)m * H_ + jj);
                float r0 = sigmoidf_((accI[0][half * 2]     + bi6[0]) + (accH[0][half * 2]     + bh6[0]));
                float r1 = sigmoidf_((accI[0][half * 2 + 1] + bi6[1]) + (accH[0][half * 2 + 1] + bh6[1]));
                float u0 = sigmoidf_((accI[1][half * 2]     + bi6[2]) + (accH[1][half * 2]     + bh6[2]));
                float u1 = sigmoidf_((accI[1][half * 2 + 1] + bi6[3]) + (accH[1][half * 2 + 1] + bh6[3]));
                float n0 = tanhf((accI[2][half * 2]     + bi6[4]) + r0 * (accH[2][half * 2]     + bh6[4]));
                float n1 = tanhf((accI[2][half * 2 + 1] + bi6[5]) + r1 * (accH[2][half * 2 + 1] + bh6[5]));
                float v0 = (1.f - u0) * n0 + u0 * hp.x;
                float v1 = (1.f - u1) * n1 + u1 * hp.y;
                *(float2*)(g_h1[nxt] + (long)m * H_ + jj) = make_float2(v0, v1);
                *(float2*)(g_h1all + ((long)m * T_ + t) * H_ + jj) = make_float2(v0, v1);
                __nv_bfloat16 h0b = __float2bfloat16(v0);
                __nv_bfloat16 h1b = __float2bfloat16(v1);
                *(__nv_bfloat162*)(g_h1hi[nxt] + (long)m * H_ + jj) = __nv_bfloat162(h0b, h1b);
                *(__nv_bfloat162*)(g_h1lo[nxt] + (long)m * H_ + jj) = __nv_bfloat162(
                    __float2bfloat16(v0 - __bfloat162float(h0b)),
                    __float2bfloat16(v1 - __bfloat162float(h1b)));
            }
        }
        grid_barrier();
    }
}

// ------------------------------- fp32 GEMM ----------------------------------
// C[M,N] = A[M,K] (row-major) @ W[N,K]^T (row-major) + bias  (f32x2 packed)
struct GArgs {
    const float* A;  long lda;
    const float* W;  long ldw;
    const float* bias;
    float*       C;  long ldc;
    int M, N, K;
};

constexpr int GBM = 128, GBN = 128, GBK = 16;

__global__ void __launch_bounds__(256, 2) gemm_nt_kernel(GArgs g0, GArgs g1) {
    GArgs g = (blockIdx.z == 0) ? g0 : g1;
    const int bm = blockIdx.y * GBM;
    const int bn = blockIdx.x * GBN;
    if (bm >= g.M || bn >= g.N) return;

    __shared__ float As[GBK][GBM + 4];
    __shared__ ull   Bs[GBK][GBN + 1];

    const int tid = threadIdx.x;
    const int tx  = tid & 15;
    const int ty  = tid >> 4;
    const int r0  = ty * 8;

    ull acc[4][8];
#pragma unroll
    for (int p = 0; p < 4; p++)
#pragma unroll
        for (int c = 0; c < 8; c++) acc[p][c] = 0ull;

    for (int k0 = 0; k0 < g.K; k0 += GBK) {
#pragma unroll
        for (int i = 0; i < 8; i++) {
            int idx = tid + i * 256;
            int m = idx >> 4, kk = idx & 15;
            int gm = bm + m, gk = k0 + kk;
            float v = 0.f;
            if (gm < g.M && gk < g.K) v = g.A[(long)gm * g.lda + gk];
            As[kk][m] = v;
        }
#pragma unroll
        for (int i = 0; i < 8; i++) {
            int idx = tid + i * 256;
            int n = idx >> 4, kk = idx & 15;
            int gn = bn + n, gk = k0 + kk;
            float v = 0.f;
            if (gn < g.N && gk < g.K) v = g.W[(long)gn * g.ldw + gk];
            Bs[kk][(n & 7) * 16 + (n >> 3)] = pack2(v, v);
        }
        __syncthreads();
#pragma unroll
        for (int kk = 0; kk < GBK; kk++) {
            ull a[4], b[8];
#pragma unroll
            for (int p = 0; p < 4; p++) a[p] = *(const ull*)&As[kk][r0 + 2 * p];
#pragma unroll
            for (int c = 0; c < 8; c++) b[c] = Bs[kk][c * 16 + tx];
#pragma unroll
            for (int p = 0; p < 4; p++)
#pragma unroll
                for (int c = 0; c < 8; c++) fma2(acc[p][c], a[p], b[c]);
        }
        __syncthreads();
    }

#pragma unroll
    for (int p = 0; p < 4; p++) {
        int gm = bm + r0 + 2 * p;
#pragma unroll
        for (int c = 0; c < 8; c++) {
            int gn = bn + tx * 8 + c;
            if (gn >= g.N) continue;
            float2 v = unpack2(acc[p][c]);
            float bias = g.bias ? g.bias[gn] : 0.f;
            if (gm < g.M)     g.C[(long)gm * g.ldc + gn]       = v.x + bias;
            if (gm + 1 < g.M) g.C[(long)(gm + 1) * g.ldc + gn] = v.y + bias;
        }
    }
}

// --------------------------- elementwise kernels ---------------------------
__global__ void init_kernel(const float* __restrict__ x) {
    long stride = (long)gridDim.x * blockDim.x;
    long i0 = (long)blockIdx.x * blockDim.x + threadIdx.x;
    if (i0 == 0) { g_bar_count = 0; g_bar_gen = 0; }
    for (long i = i0; i < BH_; i += stride) {
        g_hf[0][i] = 0.f; g_hb[0][i] = 0.f;
        g_hfhi[0][i] = __nv_bfloat16(0.f); g_hflo[0][i] = __nv_bfloat16(0.f);
        g_hbhi[0][i] = __nv_bfloat16(0.f); g_hblo[0][i] = __nv_bfloat16(0.f);
    }
    for (long i = i0; i < BT_ * R_; i += stride) {
        int  r = (int)(i % R_);
        long m = i / R_;
        int  t = (int)(m % T_);
        g_decin[i] = (t == 0) ? ((r == R_ - 1) ? 1.f : 0.f) : x[i - R_];
    }
}

__global__ void convert_w_kernel(const float* __restrict__ src,
                                 __nv_bfloat16* __restrict__ hi,
                                 __nv_bfloat16* __restrict__ lo, long n) {
    long stride = (long)gridDim.x * blockDim.x;
    for (long i = (long)blockIdx.x * blockDim.x + threadIdx.x; i < n; i += stride) {
        float w = src[i];
        __nv_bfloat16 h = __float2bfloat16(w);
        hi[i] = h;
        lo[i] = __float2bfloat16(w - __bfloat162float(h));
    }
}

__global__ void henc_kernel() {
    int i = blockIdx.x * blockDim.x + threadIdx.x;
    if (i >= B_ * H_) return;
    int b = i / H_, jj = i % H_;
    g_henc[(long)b * 2 * H_ + jj]      = g_hf[0][i];
    g_henc[(long)b * 2 * H_ + H_ + jj] = g_hb[0][i];
}

__global__ void zstd_kernel(const float* __restrict__ eps,
                            const float* __restrict__ chroma,
                            const float* __restrict__ mu_out,
                            float* __restrict__ std_out,
                            float* __restrict__ z_out) {
    int b = blockIdx.x;
    int jj = threadIdx.x;
    if (jj < Z2_) {
        float mu = mu_out[(long)b * Z2_ + jj];
        float sd = expf(g_var[(long)b * Z2_ + jj]);
        float z  = mu + sd * eps[(long)b * Z2_ + jj];
        std_out[(long)b * Z2_ + jj] = sd;
        z_out[(long)b * ZC_ + jj]   = z;
        g_zbuf[(long)b * ZC_ + jj]  = z;
    } else if (jj < ZC_) {
        float cv = chroma[(long)b * C_ + (jj - Z2_)];
        z_out[(long)b * ZC_ + jj]  = cv;
        g_zbuf[(long)b * ZC_ + jj] = cv;
    }
}

__global__ void logsoftmax_kernel(const float* __restrict__ logits,
                                  float* __restrict__ out) {
    long warp = ((long)blockIdx.x * blockDim.x + threadIdx.x) >> 5;
    int  lane = threadIdx.x & 31;
    if (warp >= BT_) return;
    const float* row = logits + warp * R_;
    float mx = -1e30f;
    for (int jj = lane; jj < R_; jj += 32) mx = fmaxf(mx, row[jj]);
#pragma unroll
    for (int o = 16; o; o >>= 1) mx = fmaxf(mx, __shfl_xor_sync(0xffffffff, mx, o));
    float s = 0.f;
    for (int jj = lane; jj < R_; jj += 32) s += expf(row[jj] - mx);
#pragma unroll
    for (int o = 16; o; o >>= 1) s += __shfl_xor_sync(0xffffffff, s, o);
    float lse = mx + logf(s);
    float* orow = out + warp * R_;
    for (int jj = lane; jj < R_; jj += 32) orow[jj] = row[jj] - lse;
}

// ------------------------------ host helpers -------------------------------
static void launch_gemm(const GArgs& a) {
    dim3 grid((a.N + GBN - 1) / GBN, (a.M + GBM - 1) / GBM, 1);
    gemm_nt_kernel<<<grid, 256>>>(a, a);
}
static void launch_gemm2(const GArgs& a, const GArgs& b) {
    int M = a.M > b.M ? a.M : b.M;
    int N = a.N > b.N ? a.N : b.N;
    dim3 grid((N + GBN - 1) / GBN, (M + GBM - 1) / GBM, 2);
    gemm_nt_kernel<<<grid, 256>>>(a, b);
}
template <typename Tp>
static float* sym_addr(Tp& sym) {
    void* p = nullptr;
    cudaGetSymbolAddress(&p, sym);
    return (float*)p;
}
template <typename Tp>
static __nv_bfloat16* sym_addr_bf(Tp& sym) {
    void* p = nullptr;
    cudaGetSymbolAddress(&p, sym);
    return (__nv_bfloat16*)p;
}

} // anonymous namespace

extern "C" void kernel_launch(void* const* d_in, const int* in_sizes, int n_in,
                              void* d_out, int out_size) {
    (void)in_sizes; (void)n_in; (void)out_size;
    const float* x        = (const float*)d_in[0];
    const float* chroma   = (const float*)d_in[1];
    const float* eps      = (const float*)d_in[2];
    const float* w_ih_f   = (const float*)d_in[3];
    const float* w_hh_f   = (const float*)d_in[4];
    const float* b_ih_f   = (const float*)d_in[5];
    const float* b_hh_f   = (const float*)d_in[6];
    const float* w_ih_b   = (const float*)d_in[7];
    const float* w_hh_b   = (const float*)d_in[8];
    const float* b_ih_b   = (const float*)d_in[9];
    const float* b_hh_b   = (const float*)d_in[10];
    const float* w_mu     = (const float*)d_in[11];
    const float* b_mu     = (const float*)d_in[12];
    const float* w_var    = (const float*)d_in[13];
    const float* b_var    = (const float*)d_in[14];
    const float* w_init   = (const float*)d_in[15];
    const float* b_init   = (const float*)d_in[16];
    const float* w_ih_g   = (const float*)d_in[17];
    const float* w_hh_g   = (const float*)d_in[18];
    const float* b_ih_g   = (const float*)d_in[19];
    const float* b_hh_g   = (const float*)d_in[20];
    const float* w_ih_g2  = (const float*)d_in[21];
    const float* w_hh_g2  = (const float*)d_in[22];
    const float* b_ih_g2  = (const float*)d_in[23];
    const float* b_hh_g2  = (const float*)d_in[24];
    const float* w_out    = (const float*)d_in[25];
    const float* b_out    = (const float*)d_in[26];

    float* out = (float*)d_out;
    const long MU_OFF  = BT_ * R_;
    const long STD_OFF = MU_OFF + (long)B_ * Z2_;
    const long Z_OFF   = STD_OFF + (long)B_ * Z2_;

    float* p_gif   = sym_addr(g_gif);
    float* p_gib   = sym_addr(g_gib);
    float* p_gid   = sym_addr(g_gid);
    float* p_zi    = sym_addr(g_zi);
    float* p_h0    = sym_addr(g_h0);
    float* p_h1all = sym_addr(g_h1all);
    float* p_henc  = sym_addr(g_henc);
    float* p_var   = sym_addr(g_var);
    float* p_zbuf  = sym_addr(g_zbuf);
    float* p_decin = sym_addr(g_decin);
    float* p_logit = sym_addr(g_logits);

    // allow >48KB dynamic smem for the persistent kernels (idempotent)
    cudaFuncSetAttribute(encoder_kernel, cudaFuncAttributeMaxDynamicSharedMemorySize, SMEM_DYN);
    cudaFuncSetAttribute(decoder_kernel, cudaFuncAttributeMaxDynamicSharedMemorySize, SMEM_DYN);

    // 1. prologue: zero h (fp32 + bf16), reset barrier, build dec_in
    init_kernel<<<512, 256>>>(x);

    // 1b. convert recurrent weights to split-bf16 (hi/lo)
    convert_w_kernel<<<512, 256>>>(w_hh_f,  sym_addr_bf(g_whhf_hi),  sym_addr_bf(g_whhf_lo),  WN_);
    convert_w_kernel<<<512, 256>>>(w_hh_b,  sym_addr_bf(g_whhb_hi),  sym_addr_bf(g_whhb_lo),  WN_);
    convert_w_kernel<<<512, 256>>>(w_hh_g,  sym_addr_bf(g_whhg_hi),  sym_addr_bf(g_whhg_lo),  WN_);
    convert_w_kernel<<<512, 256>>>(w_ih_g2, sym_addr_bf(g_wihg2_hi), sym_addr_bf(g_wihg2_lo), WN_);
    convert_w_kernel<<<512, 256>>>(w_hh_g2, sym_addr_bf(g_whhg2_hi), sym_addr_bf(g_whhg2_lo), WN_);

    // 2. encoder input gates for all timesteps (both directions)
    GArgs gif{x, R_, w_ih_f, R_, b_ih_f, p_gif, H3_, (int)BT_, H3_, R_};
    GArgs gib{x, R_, w_ih_b, R_, b_ih_b, p_gib, H3_, (int)BT_, H3_, R_};
    launch_gemm2(gif, gib);

    // 3. decoder dec_in input gates (first 130 cols of w_ih_g)
    GArgs gid{p_decin, R_, w_ih_g, 410, nullptr, p_gid, H3_, (int)BT_, H3_, R_};
    launch_gemm(gid);

    // 4. persistent bidirectional encoder recurrence (tensor cores)
    encoder_kernel<<<NB, 256, SMEM_DYN>>>(b_hh_f, b_hh_b);

    // 5. concat final hiddens
    henc_kernel<<<(B_ * H_ + 255) / 256, 256>>>();

    // 6. VAE head
    GArgs gmu {p_henc, 2 * H_, w_mu,  2 * H_, b_mu,  out + MU_OFF, Z2_, B_, Z2_, 2 * H_};
    GArgs gvar{p_henc, 2 * H_, w_var, 2 * H_, b_var, p_var,        Z2_, B_, Z2_, 2 * H_};
    launch_gemm2(gmu, gvar);

    // 7. reparameterize + concat chroma
    zstd_kernel<<<B_, 288>>>(eps, chroma, out + MU_OFF, out + STD_OFF, out + Z_OFF);

    // 8. hx0 = z @ w_init^T + b_init ; zi = z @ w_ih_g[:,130:]^T + b_ih_g
    GArgs ghx0{p_zbuf, ZC_, w_init, ZC_, b_init, p_h0, H_, B_, H_, ZC_};
    GArgs gzi {p_zbuf, ZC_, w_ih_g + 130, 410, b_ih_g, p_zi, H3_, B_, H3_, ZC_};
    launch_gemm2(ghx0, gzi);

    // 8b. convert hx0 to split-bf16
    convert_w_kernel<<<256, 256>>>(p_h0, sym_addr_bf(g_h0hi) /* [0] */,
                                   sym_addr_bf(g_h0lo), BH_);

    // 9. persistent 2-layer decoder recurrence (tensor cores)
    decoder_kernel<<<NB, 256, SMEM_DYN>>>(b_hh_g, b_ih_g2, b_hh_g2);

    // 10. batched output projection
    GArgs glog{p_h1all, H_, w_out, H_, b_out, p_logit, R_, (int)BT_, R_, H_};
    launch_gemm(glog);

    // 11. log_softmax
    logsoftmax_kernel<<<(int)((BT_ * 32 + 255) / 256), 256>>>(p_logit, out);
}